// round 2
// baseline (speedup 1.0000x reference)
#include <cuda_runtime.h>
#include <cuda_bf16.h>

#define PMAX 118
#define NMAX 236
#define D 32
#define FULL 0xffffffffu

__device__ float  g_pstate[PMAX * D];
__device__ float  g_nstate[NMAX * D];
__device__ float  g_Ap[PMAX * D];      // W1[:, :32] @ p_state + b1
__device__ float  g_An[NMAX * D];      // W1[:, 32:] @ n_state
__device__ float  g_G[2 * D];          // G[k][t] = (Wr@W2)[k][t] * ln_g[t]
__device__ float  g_consts[4];         // sG0, sG1, d0, d1
__device__ float2 g_table[PMAX * NMAX];

__device__ __forceinline__ float silu_f(float v) {
    // v * sigmoid(v) = v / (1 + e^-v)
    return __fdividef(v, 1.0f + __expf(-v));
}

// ---------------------------------------------------------------------------
// Kernel 1: serial chains (warp0 proton, warp1 neutron) + fused tail constants
// ---------------------------------------------------------------------------
__global__ void chains_kernel(const float* __restrict__ emb,
                              const float* __restrict__ Wp, const float* __restrict__ bp,
                              const float* __restrict__ Wn, const float* __restrict__ bn,
                              const float* __restrict__ ln_g, const float* __restrict__ ln_b,
                              const float* __restrict__ W2, const float* __restrict__ b2,
                              const float* __restrict__ Wr, const float* __restrict__ br)
{
    const int wid  = threadIdx.x >> 5;
    const int lane = threadIdx.x & 31;

    if (wid == 0 || wid == 1) {
        const float* W    = (wid == 0) ? Wp : Wn;
        const float* bias = (wid == 0) ? bp : bn;
        float*       dst  = (wid == 0) ? g_pstate : g_nstate;
        const int    len  = (wid == 0) ? PMAX : NMAX;

        // each lane owns one output dim: its row of W in registers
        float w[D];
        #pragma unroll
        for (int j = 0; j < D; j++) w[j] = W[lane * D + j];
        const float b = bias[lane];

        float p = emb[wid * D + lane];

        for (int s = 0; s < len; s++) {
            float sp = silu_f(p);
            float a0 = b, a1 = 0.f, a2 = 0.f, a3 = 0.f;
            #pragma unroll
            for (int j = 0; j < D; j += 4) {
                a0 = fmaf(w[j + 0], __shfl_sync(FULL, sp, j + 0), a0);
                a1 = fmaf(w[j + 1], __shfl_sync(FULL, sp, j + 1), a1);
                a2 = fmaf(w[j + 2], __shfl_sync(FULL, sp, j + 2), a2);
                a3 = fmaf(w[j + 3], __shfl_sync(FULL, sp, j + 3), a3);
            }
            p = (a0 + a1) + (a2 + a3);
            dst[s * D + lane] = p;
        }
    } else if (wid == 2) {
        // fused tail constants: M = Wr @ W2 (2 x 32); fold LN affine + biases
        const int t = lane;
        float m0 = 0.f, m1 = 0.f;
        #pragma unroll
        for (int u = 0; u < D; u++) {
            const float w2 = W2[u * D + t];
            m0 = fmaf(Wr[u],     w2, m0);
            m1 = fmaf(Wr[D + u], w2, m1);
        }
        const float g  = ln_g[t];
        const float lb = ln_b[t];
        const float G0 = m0 * g;
        const float G1 = m1 * g;
        g_G[t]     = G0;
        g_G[D + t] = G1;

        float sG0 = G0;
        float sG1 = G1;
        float d0  = fmaf(m0, lb, Wr[t]     * b2[t]);
        float d1  = fmaf(m1, lb, Wr[D + t] * b2[t]);
        #pragma unroll
        for (int off = 16; off > 0; off >>= 1) {
            sG0 += __shfl_xor_sync(FULL, sG0, off);
            sG1 += __shfl_xor_sync(FULL, sG1, off);
            d0  += __shfl_xor_sync(FULL, d0,  off);
            d1  += __shfl_xor_sync(FULL, d1,  off);
        }
        if (lane == 0) {
            g_consts[0] = sG0;
            g_consts[1] = sG1;
            g_consts[2] = d0 + br[0];
            g_consts[3] = d1 + br[1];
        }
    }
}

// ---------------------------------------------------------------------------
// Kernel 2: project states through W1 (Ap includes b1)
// warp w < PMAX: proton row; warp w - PMAX: neutron row
// ---------------------------------------------------------------------------
__global__ void project_kernel(const float* __restrict__ W1,
                               const float* __restrict__ b1)
{
    const int w    = blockIdx.x * (blockDim.x >> 5) + (threadIdx.x >> 5);
    const int lane = threadIdx.x & 31;
    if (w >= PMAX + NMAX) return;

    if (w < PMAX) {
        const float s = g_pstate[w * D + lane];
        float acc = b1[lane];
        #pragma unroll
        for (int j = 0; j < D; j++)
            acc = fmaf(W1[lane * (2 * D) + j], __shfl_sync(FULL, s, j), acc);
        g_Ap[w * D + lane] = acc;
    } else {
        const int i = w - PMAX;
        const float s = g_nstate[i * D + lane];
        float acc = 0.f;
        #pragma unroll
        for (int j = 0; j < D; j++)
            acc = fmaf(W1[lane * (2 * D) + D + j], __shfl_sync(FULL, s, j), acc);
        g_An[i * D + lane] = acc;
    }
}

// ---------------------------------------------------------------------------
// Kernel 3: build pair table. One warp per (i, j) pair.
// out_k = rs * (dot(G_k, s) - mu * sumG_k) + d_k
// ---------------------------------------------------------------------------
__global__ void table_kernel()
{
    const int pair = blockIdx.x * (blockDim.x >> 5) + (threadIdx.x >> 5);
    const int lane = threadIdx.x & 31;
    if (pair >= PMAX * NMAX) return;

    const int i = pair / NMAX;
    const int j = pair - i * NMAX;

    const float v = g_Ap[i * D + lane] + g_An[j * D + lane];
    const float s = silu_f(v);

    float r0 = s;                 // sum s
    float r1 = s * s;             // sum s^2
    float r2 = g_G[lane] * s;     // dot G0
    float r3 = g_G[D + lane] * s; // dot G1
    #pragma unroll
    for (int off = 16; off > 0; off >>= 1) {
        r0 += __shfl_xor_sync(FULL, r0, off);
        r1 += __shfl_xor_sync(FULL, r1, off);
        r2 += __shfl_xor_sync(FULL, r2, off);
        r3 += __shfl_xor_sync(FULL, r3, off);
    }

    if (lane == 0) {
        const float mu  = r0 * (1.0f / D);
        const float var = r1 * (1.0f / D) - mu * mu;
        const float rs  = rsqrtf(var + 1e-5f);
        const float o0  = rs * (r2 - mu * g_consts[0]) + g_consts[2];
        const float o1  = rs * (r3 - mu * g_consts[1]) + g_consts[3];
        g_table[pair] = make_float2(o0, o1);
    }
}

// ---------------------------------------------------------------------------
// Kernel 4: gather. 2 batch elements per thread (int4 load, float4 store).
// ---------------------------------------------------------------------------
__global__ void gather_kernel(const int4* __restrict__ x4,
                              float4* __restrict__ out4, int n4)
{
    const int t = blockIdx.x * blockDim.x + threadIdx.x;
    if (t >= n4) return;
    const int4 v = x4[t];
    const float2 a = g_table[(v.x - 1) * NMAX + (v.y - 1)];
    const float2 b = g_table[(v.z - 1) * NMAX + (v.w - 1)];
    out4[t] = make_float4(a.x, a.y, b.x, b.y);
}

// ---------------------------------------------------------------------------
extern "C" void kernel_launch(void* const* d_in, const int* in_sizes, int n_in,
                              void* d_out, int out_size)
{
    const int*   x    = (const int*)  d_in[0];
    const float* emb  = (const float*)d_in[1];
    const float* Wp   = (const float*)d_in[2];
    const float* bp   = (const float*)d_in[3];
    const float* Wn   = (const float*)d_in[4];
    const float* bn   = (const float*)d_in[5];
    const float* W1   = (const float*)d_in[6];
    const float* b1   = (const float*)d_in[7];
    const float* ln_g = (const float*)d_in[8];
    const float* ln_b = (const float*)d_in[9];
    const float* W2   = (const float*)d_in[10];
    const float* b2   = (const float*)d_in[11];
    const float* Wr   = (const float*)d_in[12];
    const float* br   = (const float*)d_in[13];

    const int B = in_sizes[0] / 2;   // x is [B, 2]

    chains_kernel<<<1, 96>>>(emb, Wp, bp, Wn, bn, ln_g, ln_b, W2, b2, Wr, br);

    {
        const int warps  = PMAX + NMAX;          // 354
        const int wpb    = 8;                    // 256 threads
        const int blocks = (warps + wpb - 1) / wpb;
        project_kernel<<<blocks, 256>>>(W1, b1);
    }

    {
        const int pairs  = PMAX * NMAX;          // 27848
        const int wpb    = 8;
        const int blocks = (pairs + wpb - 1) / wpb;
        table_kernel<<<blocks, 256>>>();
    }

    {
        const int n4     = B / 2;                // 2 elements per thread
        const int blocks = (n4 + 255) / 256;
        gather_kernel<<<blocks, 256>>>((const int4*)x, (float4*)d_out, n4);
    }
}

// round 3
// speedup vs baseline: 2.0356x; 2.0356x over previous
#include <cuda_runtime.h>
#include <cuda_bf16.h>

#define PMAX 118
#define NMAX 236
#define D 32
#define FULL 0xffffffffu

__device__ float  g_pstate[PMAX * D];
__device__ float  g_nstate[NMAX * D];
__device__ float  g_Ap[PMAX * D];      // W1[:, :32] @ p_state + b1
__device__ float  g_An[NMAX * D];      // W1[:, 32:] @ n_state
__device__ float  g_G[2 * D];          // G[k][t] = (Wr@W2)[k][t] * ln_g[t]
__device__ float  g_consts[4];         // sG0, sG1, d0, d1
__device__ float2 g_table[PMAX * NMAX];

__device__ __forceinline__ float silu_f(float v) {
    // v * sigmoid(v) = v / (1 + e^-v)
    return __fdividef(v, 1.0f + __expf(-v));
}

// ---------------------------------------------------------------------------
// Kernel 1: serial chains (warp0 proton, warp1 neutron) + fused tail constants
// Broadcast via shared memory (1 STS + syncwarp + 8 LDS.128), NOT 32 shfls.
// ---------------------------------------------------------------------------
__global__ void chains_kernel(const float* __restrict__ emb,
                              const float* __restrict__ Wp, const float* __restrict__ bp,
                              const float* __restrict__ Wn, const float* __restrict__ bn,
                              const float* __restrict__ ln_g, const float* __restrict__ ln_b,
                              const float* __restrict__ W2, const float* __restrict__ b2,
                              const float* __restrict__ Wr, const float* __restrict__ br)
{
    __shared__ __align__(16) float sbuf[2][2][D];   // [warp][parity][lane]

    const int wid  = threadIdx.x >> 5;
    const int lane = threadIdx.x & 31;

    if (wid == 0 || wid == 1) {
        const float* W    = (wid == 0) ? Wp : Wn;
        const float* bias = (wid == 0) ? bp : bn;
        float*       dst  = (wid == 0) ? g_pstate : g_nstate;
        const int    len  = (wid == 0) ? PMAX : NMAX;

        // each lane owns one output dim: its row of W in registers
        float w[D];
        #pragma unroll
        for (int j = 0; j < D; j++) w[j] = W[lane * D + j];
        const float b = bias[lane];

        float p = emb[wid * D + lane];

        for (int s = 0; s < len; s++) {
            const int par = s & 1;
            const float sp = silu_f(p);
            sbuf[wid][par][lane] = sp;
            __syncwarp();

            const float4* v4 = (const float4*)sbuf[wid][par];
            const float4 x0 = v4[0], x1 = v4[1], x2 = v4[2], x3 = v4[3];
            const float4 x4 = v4[4], x5 = v4[5], x6 = v4[6], x7 = v4[7];

            // 8 independent accumulators, 4-deep FMA chains
            float a0 = fmaf(w[0],  x0.x, b);
            float a1 = w[4]  * x1.x;
            float a2 = w[8]  * x2.x;
            float a3 = w[12] * x3.x;
            float a4 = w[16] * x4.x;
            float a5 = w[20] * x5.x;
            float a6 = w[24] * x6.x;
            float a7 = w[28] * x7.x;

            a0 = fmaf(w[1],  x0.y, a0); a1 = fmaf(w[5],  x1.y, a1);
            a2 = fmaf(w[9],  x2.y, a2); a3 = fmaf(w[13], x3.y, a3);
            a4 = fmaf(w[17], x4.y, a4); a5 = fmaf(w[21], x5.y, a5);
            a6 = fmaf(w[25], x6.y, a6); a7 = fmaf(w[29], x7.y, a7);

            a0 = fmaf(w[2],  x0.z, a0); a1 = fmaf(w[6],  x1.z, a1);
            a2 = fmaf(w[10], x2.z, a2); a3 = fmaf(w[14], x3.z, a3);
            a4 = fmaf(w[18], x4.z, a4); a5 = fmaf(w[22], x5.z, a5);
            a6 = fmaf(w[26], x6.z, a6); a7 = fmaf(w[30], x7.z, a7);

            a0 = fmaf(w[3],  x0.w, a0); a1 = fmaf(w[7],  x1.w, a1);
            a2 = fmaf(w[11], x2.w, a2); a3 = fmaf(w[15], x3.w, a3);
            a4 = fmaf(w[19], x4.w, a4); a5 = fmaf(w[23], x5.w, a5);
            a6 = fmaf(w[27], x6.w, a6); a7 = fmaf(w[31], x7.w, a7);

            p = ((a0 + a1) + (a2 + a3)) + ((a4 + a5) + (a6 + a7));
            dst[s * D + lane] = p;
        }
    } else if (wid == 2) {
        // fused tail constants: M = Wr @ W2 (2 x 32); fold LN affine + biases
        const int t = lane;
        float m0 = 0.f, m1 = 0.f;
        #pragma unroll
        for (int u = 0; u < D; u++) {
            const float w2 = W2[u * D + t];
            m0 = fmaf(Wr[u],     w2, m0);
            m1 = fmaf(Wr[D + u], w2, m1);
        }
        const float g  = ln_g[t];
        const float lb = ln_b[t];
        const float G0 = m0 * g;
        const float G1 = m1 * g;
        g_G[t]     = G0;
        g_G[D + t] = G1;

        float sG0 = G0;
        float sG1 = G1;
        float d0  = fmaf(m0, lb, Wr[t]     * b2[t]);
        float d1  = fmaf(m1, lb, Wr[D + t] * b2[t]);
        #pragma unroll
        for (int off = 16; off > 0; off >>= 1) {
            sG0 += __shfl_xor_sync(FULL, sG0, off);
            sG1 += __shfl_xor_sync(FULL, sG1, off);
            d0  += __shfl_xor_sync(FULL, d0,  off);
            d1  += __shfl_xor_sync(FULL, d1,  off);
        }
        if (lane == 0) {
            g_consts[0] = sG0;
            g_consts[1] = sG1;
            g_consts[2] = d0 + br[0];
            g_consts[3] = d1 + br[1];
        }
    }
}

// ---------------------------------------------------------------------------
// Kernel 2: project states through W1 (Ap includes b1)
// ---------------------------------------------------------------------------
__global__ void project_kernel(const float* __restrict__ W1,
                               const float* __restrict__ b1)
{
    const int w    = blockIdx.x * (blockDim.x >> 5) + (threadIdx.x >> 5);
    const int lane = threadIdx.x & 31;
    if (w >= PMAX + NMAX) return;

    if (w < PMAX) {
        const float s = g_pstate[w * D + lane];
        float acc = b1[lane];
        #pragma unroll
        for (int j = 0; j < D; j++)
            acc = fmaf(W1[lane * (2 * D) + j], __shfl_sync(FULL, s, j), acc);
        g_Ap[w * D + lane] = acc;
    } else {
        const int i = w - PMAX;
        const float s = g_nstate[i * D + lane];
        float acc = 0.f;
        #pragma unroll
        for (int j = 0; j < D; j++)
            acc = fmaf(W1[lane * (2 * D) + D + j], __shfl_sync(FULL, s, j), acc);
        g_An[i * D + lane] = acc;
    }
}

// ---------------------------------------------------------------------------
// Kernel 3: build pair table. One warp per (i, j) pair.
// out_k = rs * (dot(G_k, s) - mu * sumG_k) + d_k
// ---------------------------------------------------------------------------
__global__ void table_kernel()
{
    const int pair = blockIdx.x * (blockDim.x >> 5) + (threadIdx.x >> 5);
    const int lane = threadIdx.x & 31;
    if (pair >= PMAX * NMAX) return;

    const int i = pair / NMAX;
    const int j = pair - i * NMAX;

    const float v = g_Ap[i * D + lane] + g_An[j * D + lane];
    const float s = silu_f(v);

    float r0 = s;                 // sum s
    float r1 = s * s;             // sum s^2
    float r2 = g_G[lane] * s;     // dot G0
    float r3 = g_G[D + lane] * s; // dot G1
    #pragma unroll
    for (int off = 16; off > 0; off >>= 1) {
        r0 += __shfl_xor_sync(FULL, r0, off);
        r1 += __shfl_xor_sync(FULL, r1, off);
        r2 += __shfl_xor_sync(FULL, r2, off);
        r3 += __shfl_xor_sync(FULL, r3, off);
    }

    if (lane == 0) {
        const float mu  = r0 * (1.0f / D);
        const float var = r1 * (1.0f / D) - mu * mu;
        const float rs  = rsqrtf(var + 1e-5f);
        const float o0  = rs * (r2 - mu * g_consts[0]) + g_consts[2];
        const float o1  = rs * (r3 - mu * g_consts[1]) + g_consts[3];
        g_table[pair] = make_float2(o0, o1);
    }
}

// ---------------------------------------------------------------------------
// Kernel 4: gather. 2 int4 (= 4 batch elements) per thread for MLP.
// Thread t handles x4[t] and x4[t+H] (fully coalesced halves).
// ---------------------------------------------------------------------------
__global__ void gather_kernel(const int4* __restrict__ x4,
                              float4* __restrict__ out4, int n4, int H)
{
    const int t = blockIdx.x * blockDim.x + threadIdx.x;
    if (t >= H) return;

    const int4 v0 = x4[t];
    const int4 v1 = x4[t + H];

    const float2 a0 = g_table[(v0.x - 1) * NMAX + (v0.y - 1)];
    const float2 b0 = g_table[(v0.z - 1) * NMAX + (v0.w - 1)];
    const float2 a1 = g_table[(v1.x - 1) * NMAX + (v1.y - 1)];
    const float2 b1 = g_table[(v1.z - 1) * NMAX + (v1.w - 1)];

    out4[t]     = make_float4(a0.x, a0.y, b0.x, b0.y);
    out4[t + H] = make_float4(a1.x, a1.y, b1.x, b1.y);
}

// tail handler for odd counts (not expected for B = 2^20, but keep correct)
__global__ void gather_tail_kernel(const int2* __restrict__ x2,
                                   float2* __restrict__ out2, int start, int n)
{
    const int t = start + blockIdx.x * blockDim.x + threadIdx.x;
    if (t >= n) return;
    const int2 v = x2[t];
    out2[t] = g_table[(v.x - 1) * NMAX + (v.y - 1)];
}

// ---------------------------------------------------------------------------
extern "C" void kernel_launch(void* const* d_in, const int* in_sizes, int n_in,
                              void* d_out, int out_size)
{
    const int*   x    = (const int*)  d_in[0];
    const float* emb  = (const float*)d_in[1];
    const float* Wp   = (const float*)d_in[2];
    const float* bp   = (const float*)d_in[3];
    const float* Wn   = (const float*)d_in[4];
    const float* bn   = (const float*)d_in[5];
    const float* W1   = (const float*)d_in[6];
    const float* b1   = (const float*)d_in[7];
    const float* ln_g = (const float*)d_in[8];
    const float* ln_b = (const float*)d_in[9];
    const float* W2   = (const float*)d_in[10];
    const float* b2   = (const float*)d_in[11];
    const float* Wr   = (const float*)d_in[12];
    const float* br   = (const float*)d_in[13];

    const int B = in_sizes[0] / 2;   // x is [B, 2]

    chains_kernel<<<1, 96>>>(emb, Wp, bp, Wn, bn, ln_g, ln_b, W2, b2, Wr, br);

    {
        const int warps  = PMAX + NMAX;          // 354
        const int blocks = (warps + 7) / 8;      // 8 warps / block
        project_kernel<<<blocks, 256>>>(W1, b1);
    }

    {
        const int pairs  = PMAX * NMAX;          // 27848
        const int blocks = (pairs + 7) / 8;
        table_kernel<<<blocks, 256>>>();
    }

    {
        const int n4 = B / 2;                    // number of int4 pairs-of-pairs
        const int H  = n4 / 2;                   // 2 int4 per thread
        if (H > 0) {
            const int blocks = (H + 255) / 256;
            gather_kernel<<<blocks, 256>>>((const int4*)x, (float4*)d_out, n4, H);
        }
        // cover any remainder elements (B not divisible by 4)
        const int done = 2 * (n4 / 2) * 2;       // elements covered by main kernel
        if (done < B) {
            const int rem = B - done;
            gather_tail_kernel<<<(rem + 255) / 256, 256>>>(
                (const int2*)x, (float2*)d_out, done, B);
        }
    }
}